// round 6
// baseline (speedup 1.0000x reference)
#include <cuda_runtime.h>
#include <math.h>
#include <stdint.h>

#define C 256
#define B 16
#define TILE 16              // rows per smem tile (16 KB)
#define DEPTH 4              // pipeline stages (power of 2)
#define NCWARPS 8            // consumer warps
#define THREADS (NCWARPS * 32 + 32)   // + 1 producer warp = 288
#define NBLOCKS 444          // 3 per SM

#define TILE_FLOATS (TILE * C)
#define SMEM_BYTES (DEPTH * TILE_FLOATS * 4 + 2 * DEPTH * 8)

typedef unsigned long long u64t;

// Scratch accumulators (device globals; re-zeroed in finalize each replay)
__device__ float g_S1[B * C];
__device__ float g_S2[B * C];
__device__ float g_Z[B];
__device__ float g_W[B];
__device__ float g_mean[C];
__device__ float g_rstd[C];

// ---------------------------------------------------------------------------
// PTX helpers
// ---------------------------------------------------------------------------
__device__ __forceinline__ uint32_t smem_u32(const void* p) {
    uint32_t a;
    asm("{ .reg .u64 t; cvta.to.shared.u64 t, %1; cvt.u32.u64 %0, t; }"
        : "=r"(a) : "l"(p));
    return a;
}
__device__ __forceinline__ void mbar_init(uint32_t mbar, uint32_t cnt) {
    asm volatile("mbarrier.init.shared.b64 [%0], %1;" :: "r"(mbar), "r"(cnt) : "memory");
}
__device__ __forceinline__ void mbar_expect_tx(uint32_t mbar, uint32_t bytes) {
    asm volatile("mbarrier.arrive.expect_tx.shared.b64 _, [%0], %1;"
                 :: "r"(mbar), "r"(bytes) : "memory");
}
__device__ __forceinline__ void mbar_arrive(uint32_t mbar) {
    asm volatile("mbarrier.arrive.shared.b64 _, [%0];" :: "r"(mbar) : "memory");
}
__device__ __forceinline__ void bulk_g2s(uint32_t dst, const void* src,
                                         uint32_t bytes, uint32_t mbar) {
    asm volatile(
        "cp.async.bulk.shared::cta.global.mbarrier::complete_tx::bytes [%0], [%1], %2, [%3];"
        :: "r"(dst), "l"(src), "r"(bytes), "r"(mbar) : "memory");
}
__device__ __forceinline__ void mbar_wait(uint32_t mbar, uint32_t parity) {
    uint32_t done;
    asm volatile(
        "{\n\t.reg .pred p;\n\t"
        "mbarrier.try_wait.parity.acquire.cta.shared::cta.b64 p, [%1], %2;\n\t"
        "selp.b32 %0, 1, 0, p;\n\t}"
        : "=r"(done) : "r"(mbar), "r"(parity) : "memory");
    if (!done) {
        asm volatile(
            "{\n\t.reg .pred P1;\n\t"
            "W_%=:\n\t"
            "mbarrier.try_wait.parity.acquire.cta.shared::cta.b64 P1, [%0], %1, 0x989680;\n\t"
            "@P1 bra.uni D_%=;\n\t"
            "bra.uni W_%=;\n\t"
            "D_%=:\n\t}"
            :: "r"(mbar), "r"(parity) : "memory");
    }
}

// ---- packed f32x2 math (sm_100+ PTX) --------------------------------------
__device__ __forceinline__ u64t fma2(u64t a, u64t b, u64t c) {
    u64t d;
    asm("fma.rn.f32x2 %0, %1, %2, %3;" : "=l"(d) : "l"(a), "l"(b), "l"(c));
    return d;
}
__device__ __forceinline__ u64t mul2(u64t a, u64t b) {
    u64t d;
    asm("mul.rn.f32x2 %0, %1, %2;" : "=l"(d) : "l"(a), "l"(b));
    return d;
}
__device__ __forceinline__ u64t pk2(float lo, float hi) {
    u64t r;
    asm("mov.b64 %0, {%1, %2};" : "=l"(r) : "f"(lo), "f"(hi));
    return r;
}
__device__ __forceinline__ float2 upk2(u64t v) {
    float2 f;
    asm("mov.b64 {%0, %1}, %2;" : "=f"(f.x), "=f"(f.y) : "l"(v));
    return f;
}

// ---------------------------------------------------------------------------
__device__ __forceinline__ void flush_acc(int segv, int lane,
                                          u64t* s1p, u64t* s2p,
                                          float zacc, float wacc) {
    int c0 = lane * 4;
    int c1 = 128 + lane * 4;
    float2 v;
    v = upk2(s1p[0]); atomicAdd(&g_S1[segv*C + c0    ], v.x); atomicAdd(&g_S1[segv*C + c0 + 1], v.y);
    v = upk2(s1p[1]); atomicAdd(&g_S1[segv*C + c0 + 2], v.x); atomicAdd(&g_S1[segv*C + c0 + 3], v.y);
    v = upk2(s1p[2]); atomicAdd(&g_S1[segv*C + c1    ], v.x); atomicAdd(&g_S1[segv*C + c1 + 1], v.y);
    v = upk2(s1p[3]); atomicAdd(&g_S1[segv*C + c1 + 2], v.x); atomicAdd(&g_S1[segv*C + c1 + 3], v.y);
    v = upk2(s2p[0]); atomicAdd(&g_S2[segv*C + c0    ], v.x); atomicAdd(&g_S2[segv*C + c0 + 1], v.y);
    v = upk2(s2p[1]); atomicAdd(&g_S2[segv*C + c0 + 2], v.x); atomicAdd(&g_S2[segv*C + c0 + 3], v.y);
    v = upk2(s2p[2]); atomicAdd(&g_S2[segv*C + c1    ], v.x); atomicAdd(&g_S2[segv*C + c1 + 1], v.y);
    v = upk2(s2p[3]); atomicAdd(&g_S2[segv*C + c1 + 2], v.x); atomicAdd(&g_S2[segv*C + c1 + 3], v.y);
    if (lane == 0) {
        atomicAdd(&g_Z[segv], zacc);
        atomicAdd(&g_W[segv], wacc);
    }
}

// packed per-lane dot partial: x (4 pairs) . w (4 pairs)
__device__ __forceinline__ float dot_pk(ulonglong2 a0, ulonglong2 a1,
                                        ulonglong2 w0, ulonglong2 w1) {
    u64t d = fma2(a0.x, w0.x, fma2(a0.y, w0.y, fma2(a1.x, w1.x, mul2(a1.y, w1.y))));
    float2 f = upk2(d);
    return f.x + f.y;
}
// packed moment accumulation for one row
__device__ __forceinline__ void accum_pk(float wr, ulonglong2 a0, ulonglong2 a1,
                                         u64t* s1p, u64t* s2p) {
    u64t wr2 = pk2(wr, wr);
    s1p[0] = fma2(wr2, a0.x, s1p[0]);
    s1p[1] = fma2(wr2, a0.y, s1p[1]);
    s1p[2] = fma2(wr2, a1.x, s1p[2]);
    s1p[3] = fma2(wr2, a1.y, s1p[3]);
    s2p[0] = fma2(wr2, mul2(a0.x, a0.x), s2p[0]);
    s2p[1] = fma2(wr2, mul2(a0.y, a0.y), s2p[1]);
    s2p[2] = fma2(wr2, mul2(a1.x, a1.x), s2p[2]);
    s2p[3] = fma2(wr2, mul2(a1.y, a1.y), s2p[3]);
}

// ---------------------------------------------------------------------------
// pass 1: warp-specialized producer (TMA bulk) + 8 consumer warps
// ---------------------------------------------------------------------------
extern __shared__ char smem_raw[];

__global__ __launch_bounds__(THREADS, 3)
void pass1_kernel(const float* __restrict__ feats,
                  const int*   __restrict__ seg,
                  const float* __restrict__ wl,
                  const float* __restrict__ bl,
                  const float* __restrict__ wg,
                  const float* __restrict__ bg,
                  int n)
{
    float* tiles = (float*)smem_raw;
    uint64_t* mbar64 = (uint64_t*)(smem_raw + (size_t)DEPTH * TILE_FLOATS * 4);

    int ntiles = (n + TILE - 1) / TILE;
    int chunk  = (ntiles + NBLOCKS - 1) / NBLOCKS;
    int t0 = blockIdx.x * chunk;
    int t1 = min(ntiles, t0 + chunk);
    int nt = t1 - t0;
    if (nt <= 0) return;

    int tid  = threadIdx.x;
    int warp = tid >> 5;
    int lane = tid & 31;

    uint32_t mb_full[DEPTH], mb_empty[DEPTH];
#pragma unroll
    for (int d = 0; d < DEPTH; d++) {
        mb_full[d]  = smem_u32(&mbar64[d]);
        mb_empty[d] = smem_u32(&mbar64[DEPTH + d]);
    }
    uint32_t tile_s[DEPTH];
#pragma unroll
    for (int d = 0; d < DEPTH; d++) tile_s[d] = smem_u32(tiles + d * TILE_FLOATS);

    if (tid == 0) {
#pragma unroll
        for (int d = 0; d < DEPTH; d++) {
            mbar_init(mb_full[d], 1);        // producer expect_tx
            mbar_init(mb_empty[d], NCWARPS); // one arrive per consumer warp
        }
    }
    __syncthreads();

    if (warp == NCWARPS) {
        // ---------------- producer warp (lane 0 only) ----------------
        if (lane == 0) {
            for (int i = 0; i < nt; i++) {
                int st = i & (DEPTH - 1);
                uint32_t parity = ((i >> 2) & 1) ^ 1;   // first DEPTH pass immediately
                mbar_wait(mb_empty[st], parity);
                int t = t0 + i;
                int rows = min(TILE, n - t * TILE);
                uint32_t bytes = (uint32_t)rows * C * 4;
                mbar_expect_tx(mb_full[st], bytes);
                bulk_g2s(tile_s[st], feats + (size_t)t * TILE_FLOATS, bytes, mb_full[st]);
            }
        }
        return;
    }

    // ---------------- consumer warps ----------------
    const ulonglong2* wl2 = (const ulonglong2*)wl;
    const ulonglong2* wg2 = (const ulonglong2*)wg;
    ulonglong2 wlA = wl2[lane], wlB = wl2[32 + lane];
    ulonglong2 wgA = wg2[lane], wgB = wg2[32 + lane];
    float blv = bl[0], bgv = bg[0];

    u64t s1p[4], s2p[4];
#pragma unroll
    for (int k = 0; k < 4; k++) { s1p[k] = 0ull; s2p[k] = 0ull; }
    float zacc = 0.f, wacc = 0.f;
    int cur = __ldg(&seg[min(n - 1, t0 * TILE + warp * 2)]);

    for (int i = 0; i < nt; i++) {
        int st = i & (DEPTH - 1);
        uint32_t parity = (i >> 2) & 1;
        mbar_wait(mb_full[st], parity);

        const float* tp = tiles + st * TILE_FLOATS;
        int base = (t0 + i) * TILE;
        int rows = min(TILE, n - base);

        int s_lo = __ldg(&seg[base]);
        int s_hi = __ldg(&seg[base + rows - 1]);

        if (s_lo == s_hi && rows == TILE) {
            // ---- fast path: whole tile one segment; warp handles 2 rows ----
            if (s_lo != cur) {
                flush_acc(cur, lane, s1p, s2p, zacc, wacc);
#pragma unroll
                for (int k = 0; k < 4; k++) { s1p[k] = 0ull; s2p[k] = 0ull; }
                zacc = 0.f; wacc = 0.f;
                cur = s_lo;
            }
            const float* rp = tp + (warp * 2) * C + lane * 4;
            ulonglong2 a0 = *(const ulonglong2*)(rp);
            ulonglong2 a1 = *(const ulonglong2*)(rp + 128);
            ulonglong2 b0 = *(const ulonglong2*)(rp + C);
            ulonglong2 b1 = *(const ulonglong2*)(rp + C + 128);

            float dla = dot_pk(a0, a1, wlA, wlB);
            float dga = dot_pk(a0, a1, wgA, wgB);
            float dlb = dot_pk(b0, b1, wlA, wlB);
            float dgb = dot_pk(b0, b1, wgA, wgB);

            // 4 interleaved butterfly chains
#pragma unroll
            for (int o = 16; o; o >>= 1) {
                dla += __shfl_xor_sync(0xffffffffu, dla, o);
                dga += __shfl_xor_sync(0xffffffffu, dga, o);
                dlb += __shfl_xor_sync(0xffffffffu, dlb, o);
                dgb += __shfl_xor_sync(0xffffffffu, dgb, o);
            }
            float ea = __expf(dga + bgv);
            float eb = __expf(dgb + bgv);
            float wra = ea / (1.0f + __expf(-(dla + blv)));
            float wrb = eb / (1.0f + __expf(-(dlb + blv)));
            zacc += ea + eb;
            wacc += wra + wrb;
            accum_pk(wra, a0, a1, s1p, s2p);
            accum_pk(wrb, b0, b1, s1p, s2p);
        } else {
            // ---- slow path: tile crosses segment boundary (<=15 tiles) ----
#pragma unroll
            for (int j = 0; j < 2; j++) {
                int lr = warp * 2 + j;
                if (lr < rows) {
                    int sv = __ldg(&seg[base + lr]);
                    if (sv != cur) {
                        flush_acc(cur, lane, s1p, s2p, zacc, wacc);
#pragma unroll
                        for (int k = 0; k < 4; k++) { s1p[k] = 0ull; s2p[k] = 0ull; }
                        zacc = 0.f; wacc = 0.f;
                        cur = sv;
                    }
                    const float* rp = tp + lr * C + lane * 4;
                    ulonglong2 x0 = *(const ulonglong2*)(rp);
                    ulonglong2 x1 = *(const ulonglong2*)(rp + 128);
                    float dl = dot_pk(x0, x1, wlA, wlB);
                    float dg = dot_pk(x0, x1, wgA, wgB);
#pragma unroll
                    for (int o = 16; o; o >>= 1) {
                        dl += __shfl_xor_sync(0xffffffffu, dl, o);
                        dg += __shfl_xor_sync(0xffffffffu, dg, o);
                    }
                    float e  = __expf(dg + bgv);
                    float wr = e / (1.0f + __expf(-(dl + blv)));
                    zacc += e;
                    wacc += wr;
                    accum_pk(wr, x0, x1, s1p, s2p);
                }
            }
        }

        if (lane == 0) mbar_arrive(mb_empty[st]);   // stage drained (this warp)
    }
    flush_acc(cur, lane, s1p, s2p, zacc, wacc);
}

// ---------------------------------------------------------------------------
// finalize: fold 16 segments into mean/rstd, then re-zero accumulators
// ---------------------------------------------------------------------------
__global__ void finalize_kernel() {
    __shared__ float invZ[B];
    __shared__ float invU;
    int t = threadIdx.x;
    if (t < B) invZ[t] = 1.0f / g_Z[t];
    __syncthreads();
    if (t == 0) {
        float U = 0.f;
        for (int b = 0; b < B; b++) U += g_W[b] * invZ[b];
        invU = 1.0f / U;
    }
    __syncthreads();
    float m1 = 0.f, m2 = 0.f;
    for (int b = 0; b < B; b++) {
        m1 += g_S1[b * C + t] * invZ[b];
        m2 += g_S2[b * C + t] * invZ[b];
    }
    float iu = invU;
    m1 *= iu;
    m2 *= iu;
    float var = m2 - m1 * m1;   // sum(weight) == 1 exactly in the math
    g_mean[t] = m1;
    g_rstd[t] = 1.0f / sqrtf(var);
    for (int b = 0; b < B; b++) {
        g_S1[b * C + t] = 0.f;
        g_S2[b * C + t] = 0.f;
    }
    if (t < B) { g_Z[t] = 0.f; g_W[t] = 0.f; }
}

// ---------------------------------------------------------------------------
// pass 2: out = (x - mean[c]) * rstd[c]
// ---------------------------------------------------------------------------
__global__ __launch_bounds__(256)
void normalize_kernel(const float* __restrict__ feats,
                      float* __restrict__ out, int total4)
{
    int base = blockIdx.x * 1024 + threadIdx.x;
    if (base >= total4) return;
    const float4* f4 = (const float4*)feats;
    float4*       o4 = (float4*)out;
    const float4* m4 = (const float4*)g_mean;
    const float4* r4 = (const float4*)g_rstd;

    int cf = base & 63;
    float4 m  = m4[cf];
    float4 rs = r4[cf];

#pragma unroll
    for (int k = 0; k < 4; k++) {
        int i = base + k * 256;
        if (i < total4) {
            float4 x = __ldcs(f4 + i);
            float4 y;
            y.x = (x.x - m.x) * rs.x;
            y.y = (x.y - m.y) * rs.y;
            y.z = (x.z - m.z) * rs.z;
            y.w = (x.w - m.w) * rs.w;
            __stcs(o4 + i, y);
        }
    }
}

// ---------------------------------------------------------------------------
extern "C" void kernel_launch(void* const* d_in, const int* in_sizes, int n_in,
                              void* d_out, int out_size) {
    const float* feats = (const float*)d_in[0];
    const int*   seg   = (const int*)  d_in[1];
    const float* wl    = (const float*)d_in[2];
    const float* bl    = (const float*)d_in[3];
    const float* wg    = (const float*)d_in[4];
    const float* bg    = (const float*)d_in[5];
    float*       out   = (float*)d_out;

    int n = in_sizes[0] / C;

    cudaFuncSetAttribute(pass1_kernel,
                         cudaFuncAttributeMaxDynamicSharedMemorySize, SMEM_BYTES);

    pass1_kernel<<<NBLOCKS, THREADS, SMEM_BYTES>>>(feats, seg, wl, bl, wg, bg, n);

    finalize_kernel<<<1, C>>>();

    int total4 = n * (C / 4);
    normalize_kernel<<<(total4 + 1023) / 1024, 256>>>(feats, out, total4);
}